// round 9
// baseline (speedup 1.0000x reference)
#include <cuda_runtime.h>
#include <cuda_fp16.h>
#include <cuda_bf16.h>
#include <cstdint>

// Problem constants
#define BB   4
#define NN   16384
#define CC   64
#define KK   16
#define OUTC 128
#define BN   65536   // BB*NN

typedef unsigned long long ull;

// packed fp32x2 fma: (d.lo,d.hi) = (a.lo*b.lo+d.lo, a.hi*b.hi+d.hi)
#define FFMA2(acc, a, b) asm("fma.rn.f32x2 %0, %1, %2, %0;" : "+l"(acc) : "l"(a), "l"(b))

static __device__ __forceinline__ float ull_hsum(ull v) {
    float2 f = *reinterpret_cast<float2*>(&v);
    return f.x + f.y;
}
static __device__ __forceinline__ ull pack_dup(float x) {
    float2 f; f.x = x; f.y = x;
    return *reinterpret_cast<ull*>(&f);
}

// ---------------- scratch (device globals; no allocation) ----------------
__device__ __half g_h[(size_t)BN * CC];     // h[j] = softmax(Wm@flat_j) ⊙ flat_j (fp16, 8MB)
__device__ float  g_pool[(size_t)BN * CC];  // pooled features fp32 (16MB)
__device__ float  g_M[CC * CC];             // sum_p pooled pooled^T
__device__ float  g_s[CC];                  // sum_p pooled
__device__ float  g_Wadj[OUTC * CC];        // a_o * Wc[o][c]
__device__ float  g_badj[OUTC];             // a_o*b_o + beta_o - mean_o*a_o

// ---------------- K1: transpose + GEMM(Wmlp, packed f32x2) + softmax + ⊙flat -> g_h (fp16)
// grid 1024 blocks (64-point tiles), 256 threads. Also zeros the moment accumulators.
__global__ void __launch_bounds__(256) k1_mlp_h(const float* __restrict__ feat,
                                               const float* __restrict__ Wm) {
    __shared__ float Ft[64 * 66];
    __shared__ float Ws[64 * 66];
    int blk = blockIdx.x;
    int b   = blk >> 8;            // 256 tiles per batch (N/64)
    int n0  = (blk & 255) << 6;
    int t   = threadIdx.x;

    // fused zeroing of moment accumulators (stream-ordered before k2's atomics)
    if (blk < 16) g_M[blk * 256 + t] = 0.f;
    if (blk == 16 && t < CC) g_s[t] = 0.f;

    const float* fb = feat + (size_t)b * CC * NN;
    // load feature tile feature[b, c, n0+i] (coalesced over i) into Ft[i][c]
#pragma unroll
    for (int r = 0; r < 16; r++) {
        int e = r * 256 + t;
        int c = e >> 6, i = e & 63;
        Ft[i * 66 + c] = fb[c * NN + n0 + i];
    }
    // load W_mlp[d][c] -> Ws[d*66+c] (c contiguous)
#pragma unroll
    for (int r = 0; r < 16; r++) {
        int e = r * 256 + t;
        int d = e >> 6, c = e & 63;
        Ws[d * 66 + c] = Wm[e];
    }
    __syncthreads();

    // GEMM: thread (i,j): pts i4..i4+3, d = j + 16q; reduction over c packed in pairs
    int i4 = (t >> 4) << 2;
    int j  = t & 15;
    ull acc[4][4];
#pragma unroll
    for (int r = 0; r < 4; r++)
#pragma unroll
        for (int q = 0; q < 4; q++) acc[r][q] = 0ull;

#pragma unroll 8
    for (int cp = 0; cp < 32; cp++) {
        int c = cp << 1;
        ull p0 = *(const ull*)&Ft[(i4 + 0) * 66 + c];
        ull p1 = *(const ull*)&Ft[(i4 + 1) * 66 + c];
        ull p2 = *(const ull*)&Ft[(i4 + 2) * 66 + c];
        ull p3 = *(const ull*)&Ft[(i4 + 3) * 66 + c];
#pragma unroll
        for (int q = 0; q < 4; q++) {
            ull w = *(const ull*)&Ws[(j + (q << 4)) * 66 + c];
            FFMA2(acc[0][q], p0, w);
            FFMA2(acc[1][q], p1, w);
            FFMA2(acc[2][q], p2, w);
            FFMA2(acc[3][q], p3, w);
        }
    }

    // softmax over d (scores ~N(0,1): no max-subtraction needed), then ⊙ flat -> fp16
    size_t pbase = ((size_t)b * NN + n0) * CC;
#pragma unroll
    for (int r = 0; r < 4; r++) {
        float e0 = __expf(ull_hsum(acc[r][0]));
        float e1 = __expf(ull_hsum(acc[r][1]));
        float e2 = __expf(ull_hsum(acc[r][2]));
        float e3 = __expf(ull_hsum(acc[r][3]));
        float sum = (e0 + e1) + (e2 + e3);
#pragma unroll
        for (int d = 8; d > 0; d >>= 1)
            sum += __shfl_xor_sync(0xffffffffu, sum, d);
        float rinv = __fdividef(1.0f, sum);
        int pt = i4 + r;
        __half* hrow = g_h + pbase + (size_t)pt * 64;
        const float* frow = &Ft[pt * 66];
        hrow[j +  0] = __float2half_rn(e0 * rinv * frow[j +  0]);
        hrow[j + 16] = __float2half_rn(e1 * rinv * frow[j + 16]);
        hrow[j + 32] = __float2half_rn(e2 * rinv * frow[j + 32]);
        hrow[j + 48] = __float2half_rn(e3 * rinv * frow[j + 48]);
    }
}

// ---------------- K2: gather-pool -> g_pool + first/second-moment partials ----------------
// grid 1024 (64-point tiles) x 256 threads. Static shared 16.9KB -> high occupancy.
__global__ void __launch_bounds__(256) k2_pool(const int* __restrict__ nidx) {
    __shared__ float Ps[64 * 66];    // [pt][c] pitch 66
    int blk = blockIdx.x;
    int b   = blk >> 8;
    int n0  = (blk & 255) << 6;
    int t   = threadIdx.x;
    int warp = t >> 5, lane = t & 31;

    // gather-pool: warp w handles points 8w..8w+7; pooled_p = sum_k h[idx[p,k]]
    size_t prow0 = ((size_t)b * NN + n0);
    int4 myi = __ldg((const int4*)(nidx + ((prow0 + warp * 8) << 4)) + lane);
#pragma unroll 1
    for (int pi = 0; pi < 8; pi++) {
        int pt = warp * 8 + pi;
        float2 a0 = {0.f, 0.f}, a1 = {0.f, 0.f};
        float2 a2 = {0.f, 0.f}, a3 = {0.f, 0.f};
#pragma unroll
        for (int k = 0; k < KK; k += 8) {
            int f = pi * 16 + k;
            int j0 = __shfl_sync(0xffffffffu, myi.x, (f + 0) >> 2);
            int j1 = __shfl_sync(0xffffffffu, myi.y, (f + 1) >> 2);
            int j2 = __shfl_sync(0xffffffffu, myi.z, (f + 2) >> 2);
            int j3 = __shfl_sync(0xffffffffu, myi.w, (f + 3) >> 2);
            int j4 = __shfl_sync(0xffffffffu, myi.x, (f + 4) >> 2);
            int j5 = __shfl_sync(0xffffffffu, myi.y, (f + 5) >> 2);
            int j6 = __shfl_sync(0xffffffffu, myi.z, (f + 6) >> 2);
            int j7 = __shfl_sync(0xffffffffu, myi.w, (f + 7) >> 2);
            __half2 v0 = __ldg((const __half2*)(g_h + ((size_t)j0 << 6)) + lane);
            __half2 v1 = __ldg((const __half2*)(g_h + ((size_t)j1 << 6)) + lane);
            __half2 v2 = __ldg((const __half2*)(g_h + ((size_t)j2 << 6)) + lane);
            __half2 v3 = __ldg((const __half2*)(g_h + ((size_t)j3 << 6)) + lane);
            __half2 v4 = __ldg((const __half2*)(g_h + ((size_t)j4 << 6)) + lane);
            __half2 v5 = __ldg((const __half2*)(g_h + ((size_t)j5 << 6)) + lane);
            __half2 v6 = __ldg((const __half2*)(g_h + ((size_t)j6 << 6)) + lane);
            __half2 v7 = __ldg((const __half2*)(g_h + ((size_t)j7 << 6)) + lane);
            float2 f0 = __half22float2(v0), f1 = __half22float2(v1);
            float2 f2 = __half22float2(v2), f3 = __half22float2(v3);
            float2 f4 = __half22float2(v4), f5 = __half22float2(v5);
            float2 f6 = __half22float2(v6), f7 = __half22float2(v7);
            a0.x += f0.x; a0.y += f0.y;  a1.x += f1.x; a1.y += f1.y;
            a2.x += f2.x; a2.y += f2.y;  a3.x += f3.x; a3.y += f3.y;
            a0.x += f4.x; a0.y += f4.y;  a1.x += f5.x; a1.y += f5.y;
            a2.x += f6.x; a2.y += f6.y;  a3.x += f7.x; a3.y += f7.y;
        }
        float2 o2;
        o2.x = (a0.x + a1.x) + (a2.x + a3.x);
        o2.y = (a0.y + a1.y) + (a2.y + a3.y);
        *(float2*)&Ps[pt * 66 + 2 * lane] = o2;
        *((float2*)(g_pool + ((prow0 + pt) << 6)) + lane) = o2;  // coalesced STG.64
    }
    __syncthreads();

    // first-moment partial: threads 0..63, channel c = t
    if (t < CC) {
        float sacc = 0.f;
#pragma unroll 8
        for (int pt = 0; pt < 64; pt++) sacc += Ps[pt * 66 + t];
        atomicAdd(&g_s[t], sacc);
    }

    // second-moment partial: M[c4+i][d4+j] += sum_pt Ps[pt][c4+i]*Ps[pt][d4+j]
    // thread tile 4x4 over the full 64x64 (16x16 thread grid). FFMA2 over j-pairs.
    int c4 = (t >> 4) << 2;
    int d4 = (t & 15) << 2;
    ull mac[4][2];
#pragma unroll
    for (int i = 0; i < 4; i++) { mac[i][0] = 0ull; mac[i][1] = 0ull; }
#pragma unroll 4
    for (int pt = 0; pt < 64; pt++) {
        const float* row = &Ps[pt * 66];
        ull q01 = *(const ull*)&row[d4];
        ull q23 = *(const ull*)&row[d4 + 2];
        float p0 = row[c4 + 0], p1 = row[c4 + 1];
        float p2 = row[c4 + 2], p3 = row[c4 + 3];
        ull pd0 = pack_dup(p0), pd1 = pack_dup(p1);
        ull pd2 = pack_dup(p2), pd3 = pack_dup(p3);
        FFMA2(mac[0][0], pd0, q01); FFMA2(mac[0][1], pd0, q23);
        FFMA2(mac[1][0], pd1, q01); FFMA2(mac[1][1], pd1, q23);
        FFMA2(mac[2][0], pd2, q01); FFMA2(mac[2][1], pd2, q23);
        FFMA2(mac[3][0], pd3, q01); FFMA2(mac[3][1], pd3, q23);
    }
#pragma unroll
    for (int i = 0; i < 4; i++) {
        float2 m01 = *reinterpret_cast<float2*>(&mac[i][0]);
        float2 m23 = *reinterpret_cast<float2*>(&mac[i][1]);
        float* mrow = &g_M[(c4 + i) * 64 + d4];
        atomicAdd(mrow + 0, m01.x);
        atomicAdd(mrow + 1, m01.y);
        atomicAdd(mrow + 2, m23.x);
        atomicAdd(mrow + 3, m23.y);
    }
}

// ---------------- K3s: fold BN affine into conv weights ----------------
// 1 block x 128 threads; thread t = output channel o.
__global__ void k3s_stats(const float* __restrict__ Wc, const float* __restrict__ bc,
                          const float* __restrict__ gamma, const float* __restrict__ beta) {
    __shared__ float Ms[64 * 64];
    __shared__ float sv[64];
    int t = threadIdx.x;
#pragma unroll
    for (int r = 0; r < 32; r++) Ms[r * 128 + t] = g_M[r * 128 + t];
    if (t < 64) sv[t] = g_s[t];
    __syncthreads();

    int o = t;
    float w[64];
#pragma unroll
    for (int c = 0; c < 64; c++) w[c] = __ldg(&Wc[o * 64 + c]);

    float dot = 0.f;    // w . s
    float quad = 0.f;   // w^T M w
#pragma unroll 2
    for (int c = 0; c < 64; c++) {
        float wc = w[c];
        dot = fmaf(wc, sv[c], dot);
        ull vc = 0ull;
        const float* mrow = &Ms[c * 64];
#pragma unroll 16
        for (int cp = 0; cp < 32; cp++) {
            ull mm = *(const ull*)&mrow[cp << 1];
            ull ww = *(const ull*)&w[cp << 1];
            FFMA2(vc, mm, ww);
        }
        quad = fmaf(wc, ull_hsum(vc), quad);
    }
    const float invn = 1.0f / (float)BN;
    float b    = __ldg(&bc[o]);
    float mean = dot * invn + b;
    float ex2  = (quad + 2.f * b * dot) * invn + b * b;
    float var  = ex2 - mean * mean;
    float a    = __ldg(&gamma[o]) * rsqrtf(var + 1e-5f);
    g_badj[o]  = fmaf(b - mean, a, __ldg(&beta[o]));
#pragma unroll
    for (int c = 0; c < 64; c++) g_Wadj[o * 64 + c] = a * w[c];
}

// ---------------- K3: pooled @ Wadj^T + badj -> normalized d_out ----------------
// grid 1024 (64-point tiles) x 256 threads. Dynamic shared: Ps[64][66] + Ws[128][66].
__global__ void __launch_bounds__(256) k3_conv(float* __restrict__ out) {
    extern __shared__ float sh[];
    float* Ps = sh;                  // [pt][c] pitch 66
    float* Ws = sh + 64 * 66;        // [o][c] pitch 66; reused as staging [o][pt] pitch 66
    int blk = blockIdx.x;
    int b   = blk >> 8;
    int n0  = (blk & 255) << 6;
    int t   = threadIdx.x;
    size_t prow0 = ((size_t)b * NN + n0);

    // load pooled tile (float2, coalesced) and adjusted weights
    const float2* gp2 = (const float2*)(g_pool + (prow0 << 6));
#pragma unroll
    for (int r = 0; r < 8; r++) {
        int e = r * 256 + t;               // 2048 float2s
        int pt = e >> 5, c2 = e & 31;
        *(float2*)&Ps[pt * 66 + (c2 << 1)] = __ldg(gp2 + e);
    }
#pragma unroll
    for (int r = 0; r < 32; r++) {
        int e = r * 256 + t;
        Ws[(e >> 6) * 66 + (e & 63)] = g_Wadj[e];
    }
    __syncthreads();

    // GEMM: thread (i,j): pts i4..i4+3, o = j + 16q, q in 0..7; c packed in pairs
    int i4 = (t >> 4) << 2;
    int j  = t & 15;
    ull acc[4][8];
#pragma unroll
    for (int r = 0; r < 4; r++)
#pragma unroll
        for (int q = 0; q < 8; q++) acc[r][q] = 0ull;

#pragma unroll 4
    for (int cp = 0; cp < 32; cp++) {
        int c = cp << 1;
        ull p0 = *(const ull*)&Ps[(i4 + 0) * 66 + c];
        ull p1 = *(const ull*)&Ps[(i4 + 1) * 66 + c];
        ull p2 = *(const ull*)&Ps[(i4 + 2) * 66 + c];
        ull p3 = *(const ull*)&Ps[(i4 + 3) * 66 + c];
#pragma unroll
        for (int q = 0; q < 8; q++) {
            ull w = *(const ull*)&Ws[(j + (q << 4)) * 66 + c];
            FFMA2(acc[0][q], p0, w);
            FFMA2(acc[1][q], p1, w);
            FFMA2(acc[2][q], p2, w);
            FFMA2(acc[3][q], p3, w);
        }
    }
    __syncthreads();
    // stage result into Ss[o][pt] (reuse Ws region, pitch 66)
    float* Ss = Ws;
#pragma unroll
    for (int q = 0; q < 8; q++) {
        int o = j + (q << 4);
        float bb = __ldg(&g_badj[o]);
#pragma unroll
        for (int r = 0; r < 4; r++)
            Ss[o * 66 + i4 + r] = ull_hsum(acc[r][q]) + bb;
    }
    __syncthreads();

    // coalesced store of the final normalized output: d_out[b, o, n0+i]
    size_t obase = (size_t)b * OUTC * NN + n0;
#pragma unroll
    for (int r = 0; r < 32; r++) {
        int e = r * 256 + t;
        int o = e >> 6, i = e & 63;
        out[obase + (size_t)o * NN + i] = Ss[o * 66 + i];
    }
}

// ---------------- launch ----------------
extern "C" void kernel_launch(void* const* d_in, const int* in_sizes, int n_in,
                              void* d_out, int out_size) {
    const float* feat  = (const float*)d_in[0];
    const int*   nidx  = (const int*)d_in[1];
    // d_in[2] = permatrix (unused by forward)
    const float* Wm    = (const float*)d_in[3];
    const float* Wc    = (const float*)d_in[4];
    const float* bc    = (const float*)d_in[5];
    const float* gamma = (const float*)d_in[6];
    const float* beta  = (const float*)d_in[7];
    float*       out   = (float*)d_out;

    const int smem_k3 = (64 * 66 + 128 * 66) * (int)sizeof(float);  // 50688 B
    cudaFuncSetAttribute(k3_conv, cudaFuncAttributeMaxDynamicSharedMemorySize, smem_k3);

    k1_mlp_h<<<BN / 64, 256>>>(feat, Wm);
    k2_pool<<<BN / 64, 256>>>(nidx);
    k3s_stats<<<1, 128>>>(Wc, bc, gamma, beta);
    k3_conv<<<BN / 64, 256, smem_k3>>>(out);
}

// round 10
// speedup vs baseline: 2.0506x; 2.0506x over previous
#include <cuda_runtime.h>
#include <cuda_fp16.h>
#include <cuda_bf16.h>
#include <cstdint>

// Problem constants
#define BB   4
#define NN   16384
#define CC   64
#define KK   16
#define OUTC 128
#define BN   65536   // BB*NN

typedef unsigned long long ull;

// packed fp32x2 fma: (d.lo,d.hi) = (a.lo*b.lo+d.lo, a.hi*b.hi+d.hi)
#define FFMA2(acc, a, b) asm("fma.rn.f32x2 %0, %1, %2, %0;" : "+l"(acc) : "l"(a), "l"(b))

static __device__ __forceinline__ float ull_hsum(ull v) {
    float2 f = *reinterpret_cast<float2*>(&v);
    return f.x + f.y;
}

// ---------------- scratch (device globals; no allocation) ----------------
__device__ __half g_h[(size_t)BN * CC];              // h[j] (fp16, 8MB)
__device__ __half g_tmp[(size_t)BB * OUTC * NN];     // unnormalized out (fp16, 16.8MB)
__device__ float g_sum[OUTC];
__device__ float g_sqs[OUTC];

// ---------------- K1: transpose + GEMM(Wmlp, packed f32x2) + softmax + ⊙flat -> g_h (fp16)
// grid 1024 blocks (64-point tiles), 256 threads.
__global__ void __launch_bounds__(256) k1_mlp_h(const float* __restrict__ feat,
                                               const float* __restrict__ Wm) {
    __shared__ float Ft[64 * 66];
    __shared__ float Ws[64 * 66];
    int blk = blockIdx.x;
    int b   = blk >> 8;            // 256 tiles per batch (N/64)
    int n0  = (blk & 255) << 6;
    int t   = threadIdx.x;

    // fused k0: zero BN accumulators (ordered before k23's atomics by stream order)
    if (blk == 0 && t < OUTC) { g_sum[t] = 0.f; g_sqs[t] = 0.f; }

    const float* fb = feat + (size_t)b * CC * NN;
    // load feature tile feature[b, c, n0+i] (coalesced over i) into Ft[i][c]
#pragma unroll
    for (int r = 0; r < 16; r++) {
        int e = r * 256 + t;
        int c = e >> 6, i = e & 63;
        Ft[i * 66 + c] = fb[c * NN + n0 + i];
    }
    // load W_mlp[d][c] -> Ws[d*66+c] (c contiguous)
#pragma unroll
    for (int r = 0; r < 16; r++) {
        int e = r * 256 + t;
        int d = e >> 6, c = e & 63;
        Ws[d * 66 + c] = Wm[e];
    }
    __syncthreads();

    // GEMM: thread (i,j): pts i4..i4+3, d = j + 16q; reduction over c packed in pairs
    int i4 = (t >> 4) << 2;
    int j  = t & 15;
    ull acc[4][4];
#pragma unroll
    for (int r = 0; r < 4; r++)
#pragma unroll
        for (int q = 0; q < 4; q++) acc[r][q] = 0ull;

#pragma unroll 8
    for (int cp = 0; cp < 32; cp++) {
        int c = cp << 1;
        ull p0 = *(const ull*)&Ft[(i4 + 0) * 66 + c];
        ull p1 = *(const ull*)&Ft[(i4 + 1) * 66 + c];
        ull p2 = *(const ull*)&Ft[(i4 + 2) * 66 + c];
        ull p3 = *(const ull*)&Ft[(i4 + 3) * 66 + c];
#pragma unroll
        for (int q = 0; q < 4; q++) {
            ull w = *(const ull*)&Ws[(j + (q << 4)) * 66 + c];
            FFMA2(acc[0][q], p0, w);
            FFMA2(acc[1][q], p1, w);
            FFMA2(acc[2][q], p2, w);
            FFMA2(acc[3][q], p3, w);
        }
    }

    // softmax over d (scores ~N(0,1): no max-subtraction needed), then ⊙ flat -> fp16
    size_t pbase = ((size_t)b * NN + n0) * CC;
#pragma unroll
    for (int r = 0; r < 4; r++) {
        float e0 = __expf(ull_hsum(acc[r][0]));
        float e1 = __expf(ull_hsum(acc[r][1]));
        float e2 = __expf(ull_hsum(acc[r][2]));
        float e3 = __expf(ull_hsum(acc[r][3]));
        float sum = (e0 + e1) + (e2 + e3);
#pragma unroll
        for (int d = 8; d > 0; d >>= 1)
            sum += __shfl_xor_sync(0xffffffffu, sum, d);
        float rinv = __fdividef(1.0f, sum);
        int pt = i4 + r;
        __half* hrow = g_h + pbase + (size_t)pt * 64;
        const float* frow = &Ft[pt * 66];
        hrow[j +  0] = __float2half_rn(e0 * rinv * frow[j +  0]);
        hrow[j + 16] = __float2half_rn(e1 * rinv * frow[j + 16]);
        hrow[j + 32] = __float2half_rn(e2 * rinv * frow[j + 32]);
        hrow[j + 48] = __float2half_rn(e3 * rinv * frow[j + 48]);
    }
}

// ---------------- K23: fused gather-pool + GEMM(Wconv packed f32x2)+bias + BN partials
//                  + fp16 store of unnormalized out
// grid 1024 (64-point tiles) x 256 threads. Dynamic shared: Ps[64][66] + Ws[128][66].
__global__ void __launch_bounds__(256) k23_pool_conv(const int* __restrict__ nidx,
                              const float* __restrict__ Wc, const float* __restrict__ bc) {
    extern __shared__ float sh[];
    float* Ps = sh;                  // [pt][c] pitch 66
    float* Ws = sh + 64 * 66;        // [o][c] pitch 66; reused as staging [o][pt] pitch 66
    int blk = blockIdx.x;
    int b   = blk >> 8;
    int n0  = (blk & 255) << 6;
    int t   = threadIdx.x;
    int warp = t >> 5, lane = t & 31;

    // load W_conv[o][c] -> Ws[o*66+c] (no sync needed before gather writes to Ps)
#pragma unroll
    for (int r = 0; r < 32; r++) {
        int e = r * 256 + t;
        Ws[(e >> 6) * 66 + (e & 63)] = Wc[e];
    }

    // gather-pool: warp w handles points 8w..8w+7; pooled_p = sum_k h[idx[p,k]]
    // All 8*16=128 neighbor indices for this warp fetched with ONE LDG.128 per lane.
    size_t prow0 = ((size_t)b * NN + n0);
    int4 myi = __ldg((const int4*)(nidx + ((prow0 + warp * 8) << 4)) + lane);
#pragma unroll 1
    for (int pi = 0; pi < 8; pi++) {
        int pt = warp * 8 + pi;
        float2 a0 = {0.f, 0.f}, a1 = {0.f, 0.f};
        float2 a2 = {0.f, 0.f}, a3 = {0.f, 0.f};
#pragma unroll
        for (int k = 0; k < KK; k += 8) {
            int f = pi * 16 + k;
            int j0 = __shfl_sync(0xffffffffu, myi.x, (f + 0) >> 2);
            int j1 = __shfl_sync(0xffffffffu, myi.y, (f + 1) >> 2);
            int j2 = __shfl_sync(0xffffffffu, myi.z, (f + 2) >> 2);
            int j3 = __shfl_sync(0xffffffffu, myi.w, (f + 3) >> 2);
            int j4 = __shfl_sync(0xffffffffu, myi.x, (f + 4) >> 2);
            int j5 = __shfl_sync(0xffffffffu, myi.y, (f + 5) >> 2);
            int j6 = __shfl_sync(0xffffffffu, myi.z, (f + 6) >> 2);
            int j7 = __shfl_sync(0xffffffffu, myi.w, (f + 7) >> 2);
            __half2 v0 = __ldg((const __half2*)(g_h + ((size_t)j0 << 6)) + lane);
            __half2 v1 = __ldg((const __half2*)(g_h + ((size_t)j1 << 6)) + lane);
            __half2 v2 = __ldg((const __half2*)(g_h + ((size_t)j2 << 6)) + lane);
            __half2 v3 = __ldg((const __half2*)(g_h + ((size_t)j3 << 6)) + lane);
            __half2 v4 = __ldg((const __half2*)(g_h + ((size_t)j4 << 6)) + lane);
            __half2 v5 = __ldg((const __half2*)(g_h + ((size_t)j5 << 6)) + lane);
            __half2 v6 = __ldg((const __half2*)(g_h + ((size_t)j6 << 6)) + lane);
            __half2 v7 = __ldg((const __half2*)(g_h + ((size_t)j7 << 6)) + lane);
            float2 f0 = __half22float2(v0), f1 = __half22float2(v1);
            float2 f2 = __half22float2(v2), f3 = __half22float2(v3);
            float2 f4 = __half22float2(v4), f5 = __half22float2(v5);
            float2 f6 = __half22float2(v6), f7 = __half22float2(v7);
            a0.x += f0.x; a0.y += f0.y;  a1.x += f1.x; a1.y += f1.y;
            a2.x += f2.x; a2.y += f2.y;  a3.x += f3.x; a3.y += f3.y;
            a0.x += f4.x; a0.y += f4.y;  a1.x += f5.x; a1.y += f5.y;
            a2.x += f6.x; a2.y += f6.y;  a3.x += f7.x; a3.y += f7.y;
        }
        float2 o2;
        o2.x = (a0.x + a1.x) + (a2.x + a3.x);
        o2.y = (a0.y + a1.y) + (a2.y + a3.y);
        *(float2*)&Ps[pt * 66 + 2 * lane] = o2;   // c = 2*lane, 2*lane+1
    }
    __syncthreads();

    // GEMM: thread (i,j): pts i4..i4+3, o = j + 16q, q in 0..7; c packed in pairs
    int i4 = (t >> 4) << 2;
    int j  = t & 15;
    ull acc[4][8];
#pragma unroll
    for (int r = 0; r < 4; r++)
#pragma unroll
        for (int q = 0; q < 8; q++) acc[r][q] = 0ull;

#pragma unroll 4
    for (int cp = 0; cp < 32; cp++) {
        int c = cp << 1;
        ull p0 = *(const ull*)&Ps[(i4 + 0) * 66 + c];
        ull p1 = *(const ull*)&Ps[(i4 + 1) * 66 + c];
        ull p2 = *(const ull*)&Ps[(i4 + 2) * 66 + c];
        ull p3 = *(const ull*)&Ps[(i4 + 3) * 66 + c];
#pragma unroll
        for (int q = 0; q < 8; q++) {
            ull w = *(const ull*)&Ws[(j + (q << 4)) * 66 + c];
            FFMA2(acc[0][q], p0, w);
            FFMA2(acc[1][q], p1, w);
            FFMA2(acc[2][q], p2, w);
            FFMA2(acc[3][q], p3, w);
        }
    }
    __syncthreads();
    // stage result into Ss[o][pt] (reuse Ws region, pitch 66)
    float* Ss = Ws;
#pragma unroll
    for (int q = 0; q < 8; q++) {
        int o = j + (q << 4);
        float bb = __ldg(&bc[o]);
#pragma unroll
        for (int r = 0; r < 4; r++)
            Ss[o * 66 + i4 + r] = ull_hsum(acc[r][q]) + bb;
    }
    __syncthreads();

    // per-block BN partials (threads 0..127: one output channel each)
    if (t < OUTC) {
        float s = 0.f, s2 = 0.f;
#pragma unroll 8
        for (int pt = 0; pt < 64; pt++) {
            float v = Ss[t * 66 + pt];
            s += v;
            s2 = fmaf(v, v, s2);
        }
        atomicAdd(&g_sum[t], s);
        atomicAdd(&g_sqs[t], s2);
    }

    // coalesced fp16 store of the unnormalized tile: g_tmp[b, o, n0+i] (half2 packed)
    size_t obase = (size_t)b * OUTC * NN + n0;    // even
#pragma unroll
    for (int r = 0; r < 16; r++) {
        int e  = r * 256 + t;       // 4096 half2 elements: o = e>>5, i2 = e&31
        int o  = e >> 5, i2 = e & 31;
        __half2 hv = __floats2half2_rn(Ss[o * 66 + 2 * i2], Ss[o * 66 + 2 * i2 + 1]);
        *((__half2*)(g_tmp + obase + (size_t)o * NN) + i2) = hv;
    }
}

// ---------------- K5: finalize BN stats per-thread + normalize fp16 tmp -> fp32 out ----------
__global__ void k5_norm(const float* __restrict__ gamma, const float* __restrict__ beta,
                        float* __restrict__ out) {
    int gi = blockIdx.x * blockDim.x + threadIdx.x;   // 0 .. 2M-1 float4s
    int o  = (gi >> 12) & (OUTC - 1);                 // 4096 float4 per (b,o) row
    const float invn = 1.0f / (float)BN;
    float mean = __ldg(&g_sum[o]) * invn;
    float var  = __ldg(&g_sqs[o]) * invn - mean * mean;
    float inv  = rsqrtf(var + 1e-5f);
    float a    = __ldg(&gamma[o]) * inv;
    float s    = __ldg(&beta[o]) - mean * a;
    const __half2* tp = (const __half2*)g_tmp + 2 * gi;
    float2 lo = __half22float2(__ldg(tp + 0));
    float2 hi = __half22float2(__ldg(tp + 1));
    float4 v;
    v.x = fmaf(lo.x, a, s);
    v.y = fmaf(lo.y, a, s);
    v.z = fmaf(hi.x, a, s);
    v.w = fmaf(hi.y, a, s);
    ((float4*)out)[gi] = v;
}

// ---------------- launch ----------------
extern "C" void kernel_launch(void* const* d_in, const int* in_sizes, int n_in,
                              void* d_out, int out_size) {
    const float* feat  = (const float*)d_in[0];
    const int*   nidx  = (const int*)d_in[1];
    // d_in[2] = permatrix (unused by forward)
    const float* Wm    = (const float*)d_in[3];
    const float* Wc    = (const float*)d_in[4];
    const float* bc    = (const float*)d_in[5];
    const float* gamma = (const float*)d_in[6];
    const float* beta  = (const float*)d_in[7];
    float*       out   = (float*)d_out;

    const int smem_k23 = (64 * 66 + 128 * 66) * (int)sizeof(float);  // 50688 B
    cudaFuncSetAttribute(k23_pool_conv, cudaFuncAttributeMaxDynamicSharedMemorySize, smem_k23);

    k1_mlp_h<<<BN / 64, 256>>>(feat, Wm);
    k23_pool_conv<<<BN / 64, 256, smem_k23>>>(nidx, Wc, bc);
    k5_norm<<<(BB * OUTC * NN / 4) / 256, 256>>>(gamma, beta, out);
}